// round 6
// baseline (speedup 1.0000x reference)
#include <cuda_runtime.h>
#include <cuda_bf16.h>
#include <cuda_fp16.h>
#include <cstdint>
#include <cstddef>

#define BATCH 4
#define MDIM  4096
#define NDIM  4096
#define DQK   256

static constexpr float LOG2E = 1.4426950408889634f;

// ---------------------------------------------------------------------------
// helpers
// ---------------------------------------------------------------------------
__device__ __forceinline__ uint32_t smem_u32(const void* p) {
    uint32_t a;
    asm("{ .reg .u64 t; cvta.to.shared.u64 t, %1; cvt.u32.u64 %0, t; }"
        : "=r"(a) : "l"(p));
    return a;
}

__device__ __forceinline__ float ex2f(float x) {
    float r; asm("ex2.approx.ftz.f32 %0, %1;" : "=f"(r) : "f"(x)); return r;
}

__device__ __forceinline__ void split_pair(float a, float b, uint32_t& hi, uint32_t& lo) {
    __nv_bfloat162 h = __floats2bfloat162_rn(a, b);
    float r0 = a - __bfloat162float(__low2bfloat16(h));
    float r1 = b - __bfloat162float(__high2bfloat16(h));
    __nv_bfloat162 l = __floats2bfloat162_rn(r0, r1);
    hi = *reinterpret_cast<uint32_t*>(&h);
    lo = *reinterpret_cast<uint32_t*>(&l);
}

__device__ __forceinline__ uint32_t pack_h2(float a, float b) {
    __half2 h = __floats2half2_rn(a, b);
    return *reinterpret_cast<uint32_t*>(&h);
}

#define LDSM_X4(r0, r1, r2, r3, a) \
    asm volatile("ldmatrix.sync.aligned.m8n8.x4.shared.b16 {%0,%1,%2,%3}, [%4];" \
                 : "=r"(r0), "=r"(r1), "=r"(r2), "=r"(r3) : "r"(a))

#define LDSM_X4T(r0, r1, r2, r3, a) \
    asm volatile("ldmatrix.sync.aligned.m8n8.x4.trans.shared.b16 {%0,%1,%2,%3}, [%4];" \
                 : "=r"(r0), "=r"(r1), "=r"(r2), "=r"(r3) : "r"(a))

#define MMA_BF16(d, a0, a1, a2, a3, b0, b1)                                    \
    asm volatile("mma.sync.aligned.m16n8k16.row.col.f32.bf16.bf16.f32 "        \
                 "{%0,%1,%2,%3}, {%4,%5,%6,%7}, {%8,%9}, {%0,%1,%2,%3};"       \
                 : "+f"((d)[0]), "+f"((d)[1]), "+f"((d)[2]), "+f"((d)[3])      \
                 : "r"(a0), "r"(a1), "r"(a2), "r"(a3), "r"(b0), "r"(b1))

#define MMA_F16(d, a0, a1, a2, a3, b0, b1)                                     \
    asm volatile("mma.sync.aligned.m16n8k16.row.col.f32.f16.f16.f32 "          \
                 "{%0,%1,%2,%3}, {%4,%5,%6,%7}, {%8,%9}, {%0,%1,%2,%3};"       \
                 : "+f"((d)[0]), "+f"((d)[1]), "+f"((d)[2]), "+f"((d)[3])      \
                 : "r"(a0), "r"(a1), "r"(a2), "r"(a3), "r"(b0), "r"(b1))

#define CP_ASYNC16(dst, src) \
    asm volatile("cp.async.cg.shared.global [%0], [%1], 16;" \
                 :: "r"(dst), "l"(src) : "memory")
#define CP_COMMIT() asm volatile("cp.async.commit_group;" ::: "memory")
#define CP_WAIT2()  asm volatile("cp.async.wait_group 2;" ::: "memory")

// ---------------------------------------------------------------------------
// scratch: fp16 Q(scaled), K, V — row-major [b*4096+row][64]
// ---------------------------------------------------------------------------
__device__ __half g_q[(size_t)BATCH * MDIM * 64];
__device__ __half g_k[(size_t)BATCH * NDIM * 64];
__device__ __half g_v[(size_t)BATCH * NDIM * 64];

// ---------------------------------------------------------------------------
// HMMA projection (bf16 hi/lo 3-MMA internally, fp16 out). Same as R5.
// ---------------------------------------------------------------------------
template <int NC, int MODE>
__device__ __forceinline__ void proj_body(
    char* sm, const float* __restrict__ A, const float* __restrict__ W,
    __half* __restrict__ o0, __half* __restrict__ o1, int bi)
{
    const uint32_t sb = smem_u32(sm);
    constexpr uint32_t OFF_AL = 16384;
    constexpr uint32_t OFF_WH = 32768;
    constexpr uint32_t OFF_WL = 32768 + NC * 128;

    const int t = threadIdx.x, w = t >> 5, lane = t & 31;
    const int mat = lane >> 3, r = lane & 7;
    const int g = lane >> 2, q4 = lane & 3;
    const int r0 = bi * 128;

    float acc[NC / 8][4];
#pragma unroll
    for (int j = 0; j < NC / 8; j++)
#pragma unroll
        for (int i = 0; i < 4; i++) acc[j][i] = 0.f;

    for (int kc = 0; kc < 4; kc++) {
        if (kc) __syncthreads();
#pragma unroll
        for (int i = t; i < 2048; i += 256) {
            int row = i >> 4, c4 = i & 15;
            float4 v = *(const float4*)(A + (size_t)(r0 + row) * DQK + kc * 64 + c4 * 4);
            uint32_t h0, l0, h1, l1;
            split_pair(v.x, v.y, h0, l0);
            split_pair(v.z, v.w, h1, l1);
            uint32_t off = (uint32_t)(row * 128) + (uint32_t)((c4 * 8) ^ ((row & 7) << 4));
            *(uint2*)(sm + off)          = make_uint2(h0, h1);
            *(uint2*)(sm + OFF_AL + off) = make_uint2(l0, l1);
        }
#pragma unroll
        for (int i = t; i < 16 * NC; i += 256) {
            int kr = i / (NC / 4), c4 = i % (NC / 4);
            float4 v = *(const float4*)(W + (size_t)(kc * 64 + kr) * NC + c4 * 4);
            uint32_t h0, l0, h1, l1;
            split_pair(v.x, v.y, h0, l0);
            split_pair(v.z, v.w, h1, l1);
            uint32_t bc = (uint32_t)(c4 * 8);
            uint32_t off = (uint32_t)(kr * NC * 2) + (bc & ~127u)
                         + ((bc & 127u) ^ (uint32_t)((kr & 7) << 4));
            *(uint2*)(sm + OFF_WH + off) = make_uint2(h0, h1);
            *(uint2*)(sm + OFF_WL + off) = make_uint2(l0, l1);
        }
        __syncthreads();

        uint32_t ah[4][4], al[4][4];
#pragma unroll
        for (int kf = 0; kf < 4; kf++) {
            uint32_t off = (uint32_t)((w * 16 + (mat & 1) * 8 + r) * 128)
                         + (uint32_t)((kf * 32 + (mat >> 1) * 16) ^ (r << 4));
            LDSM_X4(ah[kf][0], ah[kf][1], ah[kf][2], ah[kf][3], sb + off);
            LDSM_X4(al[kf][0], al[kf][1], al[kf][2], al[kf][3], sb + OFF_AL + off);
        }

#pragma unroll
        for (int np = 0; np < NC / 16; np++) {
#pragma unroll
            for (int kf = 0; kf < 4; kf++) {
                int krow = kf * 16 + (mat & 1) * 8 + r;
                uint32_t bc = (uint32_t)(np * 32 + (mat >> 1) * 16);
                uint32_t off = (uint32_t)(krow * NC * 2) + (bc & ~127u)
                             + ((bc & 127u) ^ (uint32_t)((krow & 7) << 4));
                uint32_t b0, b1, b2, b3;
                LDSM_X4T(b0, b1, b2, b3, sb + OFF_WH + off);
                MMA_BF16(acc[2 * np],     ah[kf][0], ah[kf][1], ah[kf][2], ah[kf][3], b0, b1);
                MMA_BF16(acc[2 * np + 1], ah[kf][0], ah[kf][1], ah[kf][2], ah[kf][3], b2, b3);
                MMA_BF16(acc[2 * np],     al[kf][0], al[kf][1], al[kf][2], al[kf][3], b0, b1);
                MMA_BF16(acc[2 * np + 1], al[kf][0], al[kf][1], al[kf][2], al[kf][3], b2, b3);
                LDSM_X4T(b0, b1, b2, b3, sb + OFF_WL + off);
                MMA_BF16(acc[2 * np],     ah[kf][0], ah[kf][1], ah[kf][2], ah[kf][3], b0, b1);
                MMA_BF16(acc[2 * np + 1], ah[kf][0], ah[kf][1], ah[kf][2], ah[kf][3], b2, b3);
            }
        }
    }

    const float sc = (MODE == 0) ? 0.125f : 1.f;
    const int row = r0 + w * 16 + g;
#pragma unroll
    for (int j = 0; j < NC / 8; j++) {
        uint32_t p01 = pack_h2(acc[j][0] * sc, acc[j][1] * sc);
        uint32_t p23 = pack_h2(acc[j][2] * sc, acc[j][3] * sc);
        int col = j * 8 + q4 * 2;
        __half* dst = o0;
        int cc = col;
        if (MODE == 1 && col >= 64) { dst = o1; cc = col - 64; }
        *(uint32_t*)(dst + (size_t)row * 64 + cc)       = p01;
        *(uint32_t*)(dst + (size_t)(row + 8) * 64 + cc) = p23;
    }
}

__global__ void __launch_bounds__(256, 2) proj_all(
    const float* __restrict__ x,    const float* __restrict__ Wq,
    const float* __restrict__ cond, const float* __restrict__ Wkv,
    __half* __restrict__ q, __half* __restrict__ k, __half* __restrict__ v)
{
    extern __shared__ char sm[];
    if (blockIdx.x < 128) proj_body<64, 0>(sm, x, Wq, q, nullptr, blockIdx.x);
    else                  proj_body<128, 1>(sm, cond, Wkv, k, v, blockIdx.x - 128);
}

// ---------------------------------------------------------------------------
// Attention (fp16): 1 CTA = 64 q-rows, 4 warps (16 rows/warp), 2 CTAs/SM.
// 3-stage cp.async ring (stage s at s*32KB: K@+0 16KB, V@+16KB).
// Fused mainloop: per 16-key group tp: S-MMA -> exp/pack -> PV-MMA, so
// MUFU of tp overlaps HMMA of tp+1.
// ---------------------------------------------------------------------------
__device__ __forceinline__ void issue_tile(
    uint32_t sb, uint32_t buf, int nt, int t,
    const uint4* k4, const uint4* v4)
{
    const uint4* k = k4 + nt * 1024;
    const uint4* v = v4 + nt * 1024;
#pragma unroll
    for (int i = t; i < 1024; i += 128) {
        int row = i >> 3, c = i & 7;
        uint32_t off = buf + (uint32_t)(row * 128)
                     + (uint32_t)((c * 16) ^ ((row & 7) << 4));
        CP_ASYNC16(sb + off,         k + i);
        CP_ASYNC16(sb + off + 16384, v + i);
    }
}

__global__ void __launch_bounds__(128, 2) attn_kernel(
    const __half* __restrict__ Q, const __half* __restrict__ K,
    const __half* __restrict__ V, float* __restrict__ O)
{
    extern __shared__ char smem[];
    const uint32_t sb = smem_u32(smem);

    const int t    = threadIdx.x;
    const int w    = t >> 5, lane = t & 31;
    const int g    = lane >> 2, q4 = lane & 3;
    const int mat  = lane >> 3, r = lane & 7;
    const int bb   = blockIdx.y;
    const int m0   = blockIdx.x * 64;

    // ---- stage Q (pre-scaled fp16, 64 rows) into stage0 smem, load A-frags ----
    {
        const uint4* q4p = (const uint4*)(Q + ((size_t)(bb * MDIM + m0)) * 64);
#pragma unroll
        for (int i = t; i < 512; i += 128) {
            int row = i >> 3, c = i & 7;
            uint32_t off = (uint32_t)(row * 128) + (uint32_t)((c * 16) ^ ((row & 7) << 4));
            *(uint4*)(smem + off) = q4p[i];
        }
    }
    __syncthreads();

    uint32_t qh[4][4];
#pragma unroll
    for (int kf = 0; kf < 4; kf++) {
        uint32_t off = (uint32_t)((w * 16 + (mat & 1) * 8 + r) * 128)
                     + (uint32_t)((kf * 32 + (mat >> 1) * 16) ^ (r << 4));
        LDSM_X4(qh[kf][0], qh[kf][1], qh[kf][2], qh[kf][3], sb + off);
    }
    __syncthreads();

    float oacc[8][4];
#pragma unroll
    for (int n = 0; n < 8; n++)
#pragma unroll
        for (int j = 0; j < 4; j++) oacc[n][j] = 0.f;
    float l0 = 0.f, l1 = 0.f;

    const uint4* k4 = (const uint4*)(K + (size_t)(bb * NDIM) * 64);
    const uint4* v4 = (const uint4*)(V + (size_t)(bb * NDIM) * 64);

    issue_tile(sb, 0,     0, t, k4, v4); CP_COMMIT();
    issue_tile(sb, 32768, 1, t, k4, v4); CP_COMMIT();
    issue_tile(sb, 65536, 2, t, k4, v4); CP_COMMIT();

    for (int nt = 0; nt < NDIM / 128; ++nt) {
        CP_WAIT2();
        __syncthreads();
        const uint32_t buf = (uint32_t)(nt % 3) * 32768u;

        // fused: per 16-key group tp -> S, exp, PV
#pragma unroll
        for (int tp = 0; tp < 8; tp++) {
            float s0[4] = {0.f, 0.f, 0.f, 0.f};
            float s1[4] = {0.f, 0.f, 0.f, 0.f};
            const uint32_t rowb = (uint32_t)((tp * 16 + (mat >> 1) * 8 + r) * 128);
#pragma unroll
            for (int kf = 0; kf < 4; kf++) {
                uint32_t a = sb + buf + rowb
                           + (uint32_t)((kf * 32 + (mat & 1) * 16) ^ (r << 4));
                uint32_t b0, b1, b2, b3;
                LDSM_X4(b0, b1, b2, b3, a);
                MMA_F16(s0, qh[kf][0], qh[kf][1], qh[kf][2], qh[kf][3], b0, b1);
                MMA_F16(s1, qh[kf][0], qh[kf][1], qh[kf][2], qh[kf][3], b2, b3);
            }

            float e00 = ex2f(s0[0] * LOG2E), e01 = ex2f(s0[1] * LOG2E);
            float e02 = ex2f(s0[2] * LOG2E), e03 = ex2f(s0[3] * LOG2E);
            float e10 = ex2f(s1[0] * LOG2E), e11 = ex2f(s1[1] * LOG2E);
            float e12 = ex2f(s1[2] * LOG2E), e13 = ex2f(s1[3] * LOG2E);
            l0 += e00 + e01 + e10 + e11;
            l1 += e02 + e03 + e12 + e13;
            uint32_t a0 = pack_h2(e00, e01), a1 = pack_h2(e02, e03);
            uint32_t a2 = pack_h2(e10, e11), a3 = pack_h2(e12, e13);

            const uint32_t rowa = (uint32_t)((tp * 16 + (mat & 1) * 8 + r) * 128);
#pragma unroll
            for (int hp = 0; hp < 4; hp++) {
                uint32_t av = sb + buf + 16384 + rowa
                            + (uint32_t)((hp * 32 + (mat >> 1) * 16) ^ (r << 4));
                uint32_t b0, b1, b2, b3;
                LDSM_X4T(b0, b1, b2, b3, av);
                MMA_F16(oacc[2 * hp],     a0, a1, a2, a3, b0, b1);
                MMA_F16(oacc[2 * hp + 1], a0, a1, a2, a3, b2, b3);
            }
        }

        __syncthreads();
        if (nt + 3 < NDIM / 128)
            issue_tile(sb, buf, nt + 3, t, k4, v4);
        CP_COMMIT();
    }

    // ---- epilogue ----
    l0 += __shfl_xor_sync(0xffffffffu, l0, 1);
    l0 += __shfl_xor_sync(0xffffffffu, l0, 2);
    l1 += __shfl_xor_sync(0xffffffffu, l1, 1);
    l1 += __shfl_xor_sync(0xffffffffu, l1, 2);
    const float i0 = 1.f / l0, i1 = 1.f / l1;

    float* Og  = O + ((size_t)(bb * MDIM + m0 + w * 16 + g)) * 64;
    float* Og8 = Og + 8 * 64;
#pragma unroll
    for (int n = 0; n < 8; n++) {
        int col = n * 8 + q4 * 2;
        *(float2*)(Og  + col) = make_float2(oacc[n][0] * i0, oacc[n][1] * i0);
        *(float2*)(Og8 + col) = make_float2(oacc[n][2] * i1, oacc[n][3] * i1);
    }
}

// ---------------------------------------------------------------------------
// Launch
// ---------------------------------------------------------------------------
extern "C" void kernel_launch(void* const* d_in, const int* in_sizes, int n_in,
                              void* d_out, int out_size)
{
    const float* x    = (const float*)d_in[0];
    const float* cond = (const float*)d_in[1];
    const float* Wq   = (const float*)d_in[2];
    const float* Wkv  = (const float*)d_in[3];
    float* out = (float*)d_out;

    __half *q, *k, *v;
    cudaGetSymbolAddress((void**)&q, g_q);
    cudaGetSymbolAddress((void**)&k, g_k);
    cudaGetSymbolAddress((void**)&v, g_v);

    cudaFuncSetAttribute(proj_all,
                         cudaFuncAttributeMaxDynamicSharedMemorySize, 65536);
    cudaFuncSetAttribute(attn_kernel,
                         cudaFuncAttributeMaxDynamicSharedMemorySize, 98304);

    proj_all<<<256, 256, 65536>>>(x, Wq, cond, Wkv, q, k, v);

    dim3 grid(MDIM / 64, BATCH);
    attn_kernel<<<grid, 128, 98304>>>(q, k, v, out);
}

// round 7
// speedup vs baseline: 1.0250x; 1.0250x over previous
#include <cuda_runtime.h>
#include <cuda_bf16.h>
#include <cuda_fp16.h>
#include <cstdint>
#include <cstddef>

#define BATCH 4
#define MDIM  4096
#define NDIM  4096
#define DQK   256

static constexpr float LOG2E = 1.4426950408889634f;

// ---------------------------------------------------------------------------
// helpers
// ---------------------------------------------------------------------------
__device__ __forceinline__ uint32_t smem_u32(const void* p) {
    uint32_t a;
    asm("{ .reg .u64 t; cvta.to.shared.u64 t, %1; cvt.u32.u64 %0, t; }"
        : "=r"(a) : "l"(p));
    return a;
}

__device__ __forceinline__ float ex2f(float x) {
    float r; asm("ex2.approx.ftz.f32 %0, %1;" : "=f"(r) : "f"(x)); return r;
}

__device__ __forceinline__ void split_pair(float a, float b, uint32_t& hi, uint32_t& lo) {
    __nv_bfloat162 h = __floats2bfloat162_rn(a, b);
    float r0 = a - __bfloat162float(__low2bfloat16(h));
    float r1 = b - __bfloat162float(__high2bfloat16(h));
    __nv_bfloat162 l = __floats2bfloat162_rn(r0, r1);
    hi = *reinterpret_cast<uint32_t*>(&h);
    lo = *reinterpret_cast<uint32_t*>(&l);
}

__device__ __forceinline__ uint32_t pack_h2(float a, float b) {
    __half2 h = __floats2half2_rn(a, b);
    return *reinterpret_cast<uint32_t*>(&h);
}

#define LDSM_X4(r0, r1, r2, r3, a) \
    asm volatile("ldmatrix.sync.aligned.m8n8.x4.shared.b16 {%0,%1,%2,%3}, [%4];" \
                 : "=r"(r0), "=r"(r1), "=r"(r2), "=r"(r3) : "r"(a))

#define LDSM_X4T(r0, r1, r2, r3, a) \
    asm volatile("ldmatrix.sync.aligned.m8n8.x4.trans.shared.b16 {%0,%1,%2,%3}, [%4];" \
                 : "=r"(r0), "=r"(r1), "=r"(r2), "=r"(r3) : "r"(a))

#define MMA_BF16(d, a0, a1, a2, a3, b0, b1)                                    \
    asm volatile("mma.sync.aligned.m16n8k16.row.col.f32.bf16.bf16.f32 "        \
                 "{%0,%1,%2,%3}, {%4,%5,%6,%7}, {%8,%9}, {%0,%1,%2,%3};"       \
                 : "+f"((d)[0]), "+f"((d)[1]), "+f"((d)[2]), "+f"((d)[3])      \
                 : "r"(a0), "r"(a1), "r"(a2), "r"(a3), "r"(b0), "r"(b1))

#define MMA_F16(d, a0, a1, a2, a3, b0, b1)                                     \
    asm volatile("mma.sync.aligned.m16n8k16.row.col.f32.f16.f16.f32 "          \
                 "{%0,%1,%2,%3}, {%4,%5,%6,%7}, {%8,%9}, {%0,%1,%2,%3};"       \
                 : "+f"((d)[0]), "+f"((d)[1]), "+f"((d)[2]), "+f"((d)[3])      \
                 : "r"(a0), "r"(a1), "r"(a2), "r"(a3), "r"(b0), "r"(b1))

#define CP_ASYNC16(dst, src) \
    asm volatile("cp.async.cg.shared.global [%0], [%1], 16;" \
                 :: "r"(dst), "l"(src) : "memory")
#define CP_COMMIT() asm volatile("cp.async.commit_group;" ::: "memory")
#define CP_WAIT2()  asm volatile("cp.async.wait_group 2;" ::: "memory")

// ---------------------------------------------------------------------------
// scratch: fp16 Q(scaled), K, V — row-major [b*4096+row][64]
// ---------------------------------------------------------------------------
__device__ __half g_q[(size_t)BATCH * MDIM * 64];
__device__ __half g_k[(size_t)BATCH * NDIM * 64];
__device__ __half g_v[(size_t)BATCH * NDIM * 64];

// ---------------------------------------------------------------------------
// HMMA projection (bf16 hi/lo 3-MMA internally, fp16 out). Unchanged from R5.
// ---------------------------------------------------------------------------
template <int NC, int MODE>
__device__ __forceinline__ void proj_body(
    char* sm, const float* __restrict__ A, const float* __restrict__ W,
    __half* __restrict__ o0, __half* __restrict__ o1, int bi)
{
    const uint32_t sb = smem_u32(sm);
    constexpr uint32_t OFF_AL = 16384;
    constexpr uint32_t OFF_WH = 32768;
    constexpr uint32_t OFF_WL = 32768 + NC * 128;

    const int t = threadIdx.x, w = t >> 5, lane = t & 31;
    const int mat = lane >> 3, r = lane & 7;
    const int g = lane >> 2, q4 = lane & 3;
    const int r0 = bi * 128;

    float acc[NC / 8][4];
#pragma unroll
    for (int j = 0; j < NC / 8; j++)
#pragma unroll
        for (int i = 0; i < 4; i++) acc[j][i] = 0.f;

    for (int kc = 0; kc < 4; kc++) {
        if (kc) __syncthreads();
#pragma unroll
        for (int i = t; i < 2048; i += 256) {
            int row = i >> 4, c4 = i & 15;
            float4 v = *(const float4*)(A + (size_t)(r0 + row) * DQK + kc * 64 + c4 * 4);
            uint32_t h0, l0, h1, l1;
            split_pair(v.x, v.y, h0, l0);
            split_pair(v.z, v.w, h1, l1);
            uint32_t off = (uint32_t)(row * 128) + (uint32_t)((c4 * 8) ^ ((row & 7) << 4));
            *(uint2*)(sm + off)          = make_uint2(h0, h1);
            *(uint2*)(sm + OFF_AL + off) = make_uint2(l0, l1);
        }
#pragma unroll
        for (int i = t; i < 16 * NC; i += 256) {
            int kr = i / (NC / 4), c4 = i % (NC / 4);
            float4 v = *(const float4*)(W + (size_t)(kc * 64 + kr) * NC + c4 * 4);
            uint32_t h0, l0, h1, l1;
            split_pair(v.x, v.y, h0, l0);
            split_pair(v.z, v.w, h1, l1);
            uint32_t bc = (uint32_t)(c4 * 8);
            uint32_t off = (uint32_t)(kr * NC * 2) + (bc & ~127u)
                         + ((bc & 127u) ^ (uint32_t)((kr & 7) << 4));
            *(uint2*)(sm + OFF_WH + off) = make_uint2(h0, h1);
            *(uint2*)(sm + OFF_WL + off) = make_uint2(l0, l1);
        }
        __syncthreads();

        uint32_t ah[4][4], al[4][4];
#pragma unroll
        for (int kf = 0; kf < 4; kf++) {
            uint32_t off = (uint32_t)((w * 16 + (mat & 1) * 8 + r) * 128)
                         + (uint32_t)((kf * 32 + (mat >> 1) * 16) ^ (r << 4));
            LDSM_X4(ah[kf][0], ah[kf][1], ah[kf][2], ah[kf][3], sb + off);
            LDSM_X4(al[kf][0], al[kf][1], al[kf][2], al[kf][3], sb + OFF_AL + off);
        }

#pragma unroll
        for (int np = 0; np < NC / 16; np++) {
#pragma unroll
            for (int kf = 0; kf < 4; kf++) {
                int krow = kf * 16 + (mat & 1) * 8 + r;
                uint32_t bc = (uint32_t)(np * 32 + (mat >> 1) * 16);
                uint32_t off = (uint32_t)(krow * NC * 2) + (bc & ~127u)
                             + ((bc & 127u) ^ (uint32_t)((krow & 7) << 4));
                uint32_t b0, b1, b2, b3;
                LDSM_X4T(b0, b1, b2, b3, sb + OFF_WH + off);
                MMA_BF16(acc[2 * np],     ah[kf][0], ah[kf][1], ah[kf][2], ah[kf][3], b0, b1);
                MMA_BF16(acc[2 * np + 1], ah[kf][0], ah[kf][1], ah[kf][2], ah[kf][3], b2, b3);
                MMA_BF16(acc[2 * np],     al[kf][0], al[kf][1], al[kf][2], al[kf][3], b0, b1);
                MMA_BF16(acc[2 * np + 1], al[kf][0], al[kf][1], al[kf][2], al[kf][3], b2, b3);
                LDSM_X4T(b0, b1, b2, b3, sb + OFF_WL + off);
                MMA_BF16(acc[2 * np],     ah[kf][0], ah[kf][1], ah[kf][2], ah[kf][3], b0, b1);
                MMA_BF16(acc[2 * np + 1], ah[kf][0], ah[kf][1], ah[kf][2], ah[kf][3], b2, b3);
            }
        }
    }

    const float sc = (MODE == 0) ? 0.125f : 1.f;
    const int row = r0 + w * 16 + g;
#pragma unroll
    for (int j = 0; j < NC / 8; j++) {
        uint32_t p01 = pack_h2(acc[j][0] * sc, acc[j][1] * sc);
        uint32_t p23 = pack_h2(acc[j][2] * sc, acc[j][3] * sc);
        int col = j * 8 + q4 * 2;
        __half* dst = o0;
        int cc = col;
        if (MODE == 1 && col >= 64) { dst = o1; cc = col - 64; }
        *(uint32_t*)(dst + (size_t)row * 64 + cc)       = p01;
        *(uint32_t*)(dst + (size_t)(row + 8) * 64 + cc) = p23;
    }
}

__global__ void __launch_bounds__(256, 2) proj_all(
    const float* __restrict__ x,    const float* __restrict__ Wq,
    const float* __restrict__ cond, const float* __restrict__ Wkv,
    __half* __restrict__ q, __half* __restrict__ k, __half* __restrict__ v)
{
    extern __shared__ char sm[];
    if (blockIdx.x < 128) proj_body<64, 0>(sm, x, Wq, q, nullptr, blockIdx.x);
    else                  proj_body<128, 1>(sm, cond, Wkv, k, v, blockIdx.x - 128);
}

// ---------------------------------------------------------------------------
// Attention (fp16): 1 CTA = 64 q-rows, 4 warps in 2x2 (mw x kw) tiling:
// warp (mw,kw) owns rows [mw*32,+32) x keys [kw*64,+64) of each 128-key tile.
// B-frags (K,V) reused across 2 m-tiles -> LDSM:MMA ratio 1:4.
// O/l partial over keys; cross-kw smem reduction in epilogue.
// 3-stage cp.async ring (stage s at s*32KB: K@+0 16KB, V@+16KB).
// ---------------------------------------------------------------------------
__device__ __forceinline__ void issue_tile(
    uint32_t sb, uint32_t buf, int nt, int t,
    const uint4* k4, const uint4* v4)
{
    const uint4* k = k4 + nt * 1024;
    const uint4* v = v4 + nt * 1024;
#pragma unroll
    for (int i = t; i < 1024; i += 128) {
        int row = i >> 3, c = i & 7;
        uint32_t off = buf + (uint32_t)(row * 128)
                     + (uint32_t)((c * 16) ^ ((row & 7) << 4));
        CP_ASYNC16(sb + off,         k + i);
        CP_ASYNC16(sb + off + 16384, v + i);
    }
}

__global__ void __launch_bounds__(128, 2) attn_kernel(
    const __half* __restrict__ Q, const __half* __restrict__ K,
    const __half* __restrict__ V, float* __restrict__ O)
{
    extern __shared__ char smem[];
    const uint32_t sb = smem_u32(smem);

    const int t    = threadIdx.x;
    const int w    = t >> 5, lane = t & 31;
    const int mw   = w >> 1, kw = w & 1;
    const int g    = lane >> 2, q4 = lane & 3;
    const int mat  = lane >> 3, r = lane & 7;
    const int bb   = blockIdx.y;
    const int m0   = blockIdx.x * 64;

    // ---- stage Q (pre-scaled fp16, 64 rows) into stage0, load A-frags ----
    {
        const uint4* q4p = (const uint4*)(Q + ((size_t)(bb * MDIM + m0)) * 64);
#pragma unroll
        for (int i = t; i < 512; i += 128) {
            int row = i >> 3, c = i & 7;
            uint32_t off = (uint32_t)(row * 128) + (uint32_t)((c * 16) ^ ((row & 7) << 4));
            *(uint4*)(smem + off) = q4p[i];
        }
    }
    __syncthreads();

    uint32_t qh[2][4][4];   // mt x kf x 4
#pragma unroll
    for (int mt = 0; mt < 2; mt++)
#pragma unroll
        for (int kf = 0; kf < 4; kf++) {
            uint32_t off = (uint32_t)((mw * 32 + mt * 16 + (mat & 1) * 8 + r) * 128)
                         + (uint32_t)((kf * 32 + (mat >> 1) * 16) ^ (r << 4));
            LDSM_X4(qh[mt][kf][0], qh[mt][kf][1], qh[mt][kf][2], qh[mt][kf][3],
                    sb + off);
        }
    __syncthreads();

    float oacc[2][8][4];    // mt x h-block x 4
#pragma unroll
    for (int mt = 0; mt < 2; mt++)
#pragma unroll
        for (int n = 0; n < 8; n++)
#pragma unroll
            for (int j = 0; j < 4; j++) oacc[mt][n][j] = 0.f;
    float ll[2][2] = {{0.f, 0.f}, {0.f, 0.f}};

    const uint4* k4 = (const uint4*)(K + (size_t)(bb * NDIM) * 64);
    const uint4* v4 = (const uint4*)(V + (size_t)(bb * NDIM) * 64);

    issue_tile(sb, 0,     0, t, k4, v4); CP_COMMIT();
    issue_tile(sb, 32768, 1, t, k4, v4); CP_COMMIT();
    issue_tile(sb, 65536, 2, t, k4, v4); CP_COMMIT();

    for (int nt = 0; nt < NDIM / 128; ++nt) {
        CP_WAIT2();
        __syncthreads();
        const uint32_t buf = (uint32_t)(nt % 3) * 32768u;

#pragma unroll
        for (int tp = 0; tp < 4; tp++) {
            const int kg = kw * 4 + tp;   // 16-key group within the 128-key tile

            // K B-frags for these 16 keys (reused by both m-tiles)
            uint32_t kb[4][4];
            const uint32_t rowb = (uint32_t)((kg * 16 + (mat >> 1) * 8 + r) * 128);
#pragma unroll
            for (int kf = 0; kf < 4; kf++) {
                uint32_t a = sb + buf + rowb
                           + (uint32_t)((kf * 32 + (mat & 1) * 16) ^ (r << 4));
                LDSM_X4(kb[kf][0], kb[kf][1], kb[kf][2], kb[kf][3], a);
            }

            // S for both m-tiles
            float s[2][2][4];
#pragma unroll
            for (int mt = 0; mt < 2; mt++) {
#pragma unroll
                for (int nb = 0; nb < 2; nb++)
#pragma unroll
                    for (int j = 0; j < 4; j++) s[mt][nb][j] = 0.f;
#pragma unroll
                for (int kf = 0; kf < 4; kf++) {
                    MMA_F16(s[mt][0], qh[mt][kf][0], qh[mt][kf][1],
                            qh[mt][kf][2], qh[mt][kf][3], kb[kf][0], kb[kf][1]);
                    MMA_F16(s[mt][1], qh[mt][kf][0], qh[mt][kf][1],
                            qh[mt][kf][2], qh[mt][kf][3], kb[kf][2], kb[kf][3]);
                }
            }

            // exp, row sums, pack to A-frags
            uint32_t pa[2][4];
#pragma unroll
            for (int mt = 0; mt < 2; mt++) {
                float e00 = ex2f(s[mt][0][0] * LOG2E), e01 = ex2f(s[mt][0][1] * LOG2E);
                float e02 = ex2f(s[mt][0][2] * LOG2E), e03 = ex2f(s[mt][0][3] * LOG2E);
                float e10 = ex2f(s[mt][1][0] * LOG2E), e11 = ex2f(s[mt][1][1] * LOG2E);
                float e12 = ex2f(s[mt][1][2] * LOG2E), e13 = ex2f(s[mt][1][3] * LOG2E);
                ll[mt][0] += e00 + e01 + e10 + e11;
                ll[mt][1] += e02 + e03 + e12 + e13;
                pa[mt][0] = pack_h2(e00, e01); pa[mt][1] = pack_h2(e02, e03);
                pa[mt][2] = pack_h2(e10, e11); pa[mt][3] = pack_h2(e12, e13);
            }

            // V B-frags (reused by both m-tiles) + PV
            const uint32_t rowa = (uint32_t)((kg * 16 + (mat & 1) * 8 + r) * 128);
#pragma unroll
            for (int hp = 0; hp < 4; hp++) {
                uint32_t av = sb + buf + 16384 + rowa
                            + (uint32_t)((hp * 32 + (mat >> 1) * 16) ^ (r << 4));
                uint32_t b0, b1, b2, b3;
                LDSM_X4T(b0, b1, b2, b3, av);
#pragma unroll
                for (int mt = 0; mt < 2; mt++) {
                    MMA_F16(oacc[mt][2 * hp],     pa[mt][0], pa[mt][1],
                            pa[mt][2], pa[mt][3], b0, b1);
                    MMA_F16(oacc[mt][2 * hp + 1], pa[mt][0], pa[mt][1],
                            pa[mt][2], pa[mt][3], b2, b3);
                }
            }
        }

        __syncthreads();
        if (nt + 3 < NDIM / 128)
            issue_tile(sb, buf, nt + 3, t, k4, v4);
        CP_COMMIT();
    }

    // ---- epilogue: quad-reduce l, cross-kw smem reduction, store ----
#pragma unroll
    for (int mt = 0; mt < 2; mt++)
#pragma unroll
        for (int h = 0; h < 2; h++) {
            ll[mt][h] += __shfl_xor_sync(0xffffffffu, ll[mt][h], 1);
            ll[mt][h] += __shfl_xor_sync(0xffffffffu, ll[mt][h], 2);
        }

    __syncthreads();   // all tile work done; stage smem is reusable
    float* Osm = (float*)smem;             // [64 rows][64 cols]
    float* lsm = (float*)(smem + 16384);   // [64 rows]

    if (kw == 1) {
#pragma unroll
        for (int mt = 0; mt < 2; mt++) {
            int rr = mw * 32 + mt * 16 + g;
            float* d0 = Osm + rr * 64;
            float* d1 = d0 + 8 * 64;
#pragma unroll
            for (int n = 0; n < 8; n++) {
                int col = n * 8 + q4 * 2;
                *(float2*)(d0 + col) = make_float2(oacc[mt][n][0], oacc[mt][n][1]);
                *(float2*)(d1 + col) = make_float2(oacc[mt][n][2], oacc[mt][n][3]);
            }
            if (q4 == 0) {
                lsm[rr]     = ll[mt][0];
                lsm[rr + 8] = ll[mt][1];
            }
        }
    }
    __syncthreads();

    if (kw == 0) {
#pragma unroll
        for (int mt = 0; mt < 2; mt++) {
            int rr = mw * 32 + mt * 16 + g;
            const float* s0 = Osm + rr * 64;
            const float* s1 = s0 + 8 * 64;
            const float i0 = 1.f / (ll[mt][0] + lsm[rr]);
            const float i1 = 1.f / (ll[mt][1] + lsm[rr + 8]);
            float* Og0 = O + ((size_t)(bb * MDIM + m0 + rr)) * 64;
            float* Og1 = Og0 + 8 * 64;
#pragma unroll
            for (int n = 0; n < 8; n++) {
                int col = n * 8 + q4 * 2;
                float2 a0 = *(const float2*)(s0 + col);
                float2 a1 = *(const float2*)(s1 + col);
                *(float2*)(Og0 + col) = make_float2((oacc[mt][n][0] + a0.x) * i0,
                                                    (oacc[mt][n][1] + a0.y) * i0);
                *(float2*)(Og1 + col) = make_float2((oacc[mt][n][2] + a1.x) * i1,
                                                    (oacc[mt][n][3] + a1.y) * i1);
            }
        }
    }
}

// ---------------------------------------------------------------------------
// Launch
// ---------------------------------------------------------------------------
extern "C" void kernel_launch(void* const* d_in, const int* in_sizes, int n_in,
                              void* d_out, int out_size)
{
    const float* x    = (const float*)d_in[0];
    const float* cond = (const float*)d_in[1];
    const float* Wq   = (const float*)d_in[2];
    const float* Wkv  = (const float*)d_in[3];
    float* out = (float*)d_out;

    __half *q, *k, *v;
    cudaGetSymbolAddress((void**)&q, g_q);
    cudaGetSymbolAddress((void**)&k, g_k);
    cudaGetSymbolAddress((void**)&v, g_v);

    cudaFuncSetAttribute(proj_all,
                         cudaFuncAttributeMaxDynamicSharedMemorySize, 65536);
    cudaFuncSetAttribute(attn_kernel,
                         cudaFuncAttributeMaxDynamicSharedMemorySize, 98304);

    proj_all<<<256, 256, 65536>>>(x, Wq, cond, Wkv, q, k, v);

    dim3 grid(MDIM / 64, BATCH);
    attn_kernel<<<grid, 128, 98304>>>(q, k, v, out);
}

// round 8
// speedup vs baseline: 1.0478x; 1.0222x over previous
#include <cuda_runtime.h>
#include <cuda_bf16.h>
#include <cuda_fp16.h>
#include <cstdint>
#include <cstddef>

#define BATCH 4
#define MDIM  4096
#define NDIM  4096
#define DQK   256

static constexpr float LOG2E = 1.4426950408889634f;

// ---------------------------------------------------------------------------
// helpers
// ---------------------------------------------------------------------------
__device__ __forceinline__ uint32_t smem_u32(const void* p) {
    uint32_t a;
    asm("{ .reg .u64 t; cvta.to.shared.u64 t, %1; cvt.u32.u64 %0, t; }"
        : "=r"(a) : "l"(p));
    return a;
}

__device__ __forceinline__ float ex2f(float x) {
    float r; asm("ex2.approx.ftz.f32 %0, %1;" : "=f"(r) : "f"(x)); return r;
}

__device__ __forceinline__ void split_pair(float a, float b, uint32_t& hi, uint32_t& lo) {
    __nv_bfloat162 h = __floats2bfloat162_rn(a, b);
    float r0 = a - __bfloat162float(__low2bfloat16(h));
    float r1 = b - __bfloat162float(__high2bfloat16(h));
    __nv_bfloat162 l = __floats2bfloat162_rn(r0, r1);
    hi = *reinterpret_cast<uint32_t*>(&h);
    lo = *reinterpret_cast<uint32_t*>(&l);
}

__device__ __forceinline__ uint32_t pack_h2(float a, float b) {
    __half2 h = __floats2half2_rn(a, b);
    return *reinterpret_cast<uint32_t*>(&h);
}

#define LDSM_X4(r0, r1, r2, r3, a) \
    asm volatile("ldmatrix.sync.aligned.m8n8.x4.shared.b16 {%0,%1,%2,%3}, [%4];" \
                 : "=r"(r0), "=r"(r1), "=r"(r2), "=r"(r3) : "r"(a))

#define LDSM_X4T(r0, r1, r2, r3, a) \
    asm volatile("ldmatrix.sync.aligned.m8n8.x4.trans.shared.b16 {%0,%1,%2,%3}, [%4];" \
                 : "=r"(r0), "=r"(r1), "=r"(r2), "=r"(r3) : "r"(a))

#define MMA_BF16(d, a0, a1, a2, a3, b0, b1)                                    \
    asm volatile("mma.sync.aligned.m16n8k16.row.col.f32.bf16.bf16.f32 "        \
                 "{%0,%1,%2,%3}, {%4,%5,%6,%7}, {%8,%9}, {%0,%1,%2,%3};"       \
                 : "+f"((d)[0]), "+f"((d)[1]), "+f"((d)[2]), "+f"((d)[3])      \
                 : "r"(a0), "r"(a1), "r"(a2), "r"(a3), "r"(b0), "r"(b1))

#define MMA_F16(d, a0, a1, a2, a3, b0, b1)                                     \
    asm volatile("mma.sync.aligned.m16n8k16.row.col.f32.f16.f16.f32 "          \
                 "{%0,%1,%2,%3}, {%4,%5,%6,%7}, {%8,%9}, {%0,%1,%2,%3};"       \
                 : "+f"((d)[0]), "+f"((d)[1]), "+f"((d)[2]), "+f"((d)[3])      \
                 : "r"(a0), "r"(a1), "r"(a2), "r"(a3), "r"(b0), "r"(b1))

#define CP_ASYNC16(dst, src) \
    asm volatile("cp.async.cg.shared.global [%0], [%1], 16;" \
                 :: "r"(dst), "l"(src) : "memory")
#define CP_COMMIT() asm volatile("cp.async.commit_group;" ::: "memory")
#define CP_WAIT2()  asm volatile("cp.async.wait_group 2;" ::: "memory")

// ---------------------------------------------------------------------------
// scratch: fp16 Q(scaled by 0.125*log2e), K, V — row-major [b*4096+row][64]
// ---------------------------------------------------------------------------
__device__ __half g_q[(size_t)BATCH * MDIM * 64];
__device__ __half g_k[(size_t)BATCH * NDIM * 64];
__device__ __half g_v[(size_t)BATCH * NDIM * 64];

// ---------------------------------------------------------------------------
// HMMA projection (bf16 hi/lo 3-MMA internally, fp16 out).
// MODE 0: scale 0.125*LOG2E (folds softmax scale AND exp2 base change into Q).
// ---------------------------------------------------------------------------
template <int NC, int MODE>
__device__ __forceinline__ void proj_body(
    char* sm, const float* __restrict__ A, const float* __restrict__ W,
    __half* __restrict__ o0, __half* __restrict__ o1, int bi)
{
    const uint32_t sb = smem_u32(sm);
    constexpr uint32_t OFF_AL = 16384;
    constexpr uint32_t OFF_WH = 32768;
    constexpr uint32_t OFF_WL = 32768 + NC * 128;

    const int t = threadIdx.x, w = t >> 5, lane = t & 31;
    const int mat = lane >> 3, r = lane & 7;
    const int g = lane >> 2, q4 = lane & 3;
    const int r0 = bi * 128;

    float acc[NC / 8][4];
#pragma unroll
    for (int j = 0; j < NC / 8; j++)
#pragma unroll
        for (int i = 0; i < 4; i++) acc[j][i] = 0.f;

    for (int kc = 0; kc < 4; kc++) {
        if (kc) __syncthreads();
#pragma unroll
        for (int i = t; i < 2048; i += 256) {
            int row = i >> 4, c4 = i & 15;
            float4 v = *(const float4*)(A + (size_t)(r0 + row) * DQK + kc * 64 + c4 * 4);
            uint32_t h0, l0, h1, l1;
            split_pair(v.x, v.y, h0, l0);
            split_pair(v.z, v.w, h1, l1);
            uint32_t off = (uint32_t)(row * 128) + (uint32_t)((c4 * 8) ^ ((row & 7) << 4));
            *(uint2*)(sm + off)          = make_uint2(h0, h1);
            *(uint2*)(sm + OFF_AL + off) = make_uint2(l0, l1);
        }
#pragma unroll
        for (int i = t; i < 16 * NC; i += 256) {
            int kr = i / (NC / 4), c4 = i % (NC / 4);
            float4 v = *(const float4*)(W + (size_t)(kc * 64 + kr) * NC + c4 * 4);
            uint32_t h0, l0, h1, l1;
            split_pair(v.x, v.y, h0, l0);
            split_pair(v.z, v.w, h1, l1);
            uint32_t bc = (uint32_t)(c4 * 8);
            uint32_t off = (uint32_t)(kr * NC * 2) + (bc & ~127u)
                         + ((bc & 127u) ^ (uint32_t)((kr & 7) << 4));
            *(uint2*)(sm + OFF_WH + off) = make_uint2(h0, h1);
            *(uint2*)(sm + OFF_WL + off) = make_uint2(l0, l1);
        }
        __syncthreads();

        uint32_t ah[4][4], al[4][4];
#pragma unroll
        for (int kf = 0; kf < 4; kf++) {
            uint32_t off = (uint32_t)((w * 16 + (mat & 1) * 8 + r) * 128)
                         + (uint32_t)((kf * 32 + (mat >> 1) * 16) ^ (r << 4));
            LDSM_X4(ah[kf][0], ah[kf][1], ah[kf][2], ah[kf][3], sb + off);
            LDSM_X4(al[kf][0], al[kf][1], al[kf][2], al[kf][3], sb + OFF_AL + off);
        }

#pragma unroll
        for (int np = 0; np < NC / 16; np++) {
#pragma unroll
            for (int kf = 0; kf < 4; kf++) {
                int krow = kf * 16 + (mat & 1) * 8 + r;
                uint32_t bc = (uint32_t)(np * 32 + (mat >> 1) * 16);
                uint32_t off = (uint32_t)(krow * NC * 2) + (bc & ~127u)
                             + ((bc & 127u) ^ (uint32_t)((krow & 7) << 4));
                uint32_t b0, b1, b2, b3;
                LDSM_X4T(b0, b1, b2, b3, sb + OFF_WH + off);
                MMA_BF16(acc[2 * np],     ah[kf][0], ah[kf][1], ah[kf][2], ah[kf][3], b0, b1);
                MMA_BF16(acc[2 * np + 1], ah[kf][0], ah[kf][1], ah[kf][2], ah[kf][3], b2, b3);
                MMA_BF16(acc[2 * np],     al[kf][0], al[kf][1], al[kf][2], al[kf][3], b0, b1);
                MMA_BF16(acc[2 * np + 1], al[kf][0], al[kf][1], al[kf][2], al[kf][3], b2, b3);
                LDSM_X4T(b0, b1, b2, b3, sb + OFF_WL + off);
                MMA_BF16(acc[2 * np],     ah[kf][0], ah[kf][1], ah[kf][2], ah[kf][3], b0, b1);
                MMA_BF16(acc[2 * np + 1], ah[kf][0], ah[kf][1], ah[kf][2], ah[kf][3], b2, b3);
            }
        }
    }

    const float sc = (MODE == 0) ? 0.125f * LOG2E : 1.f;
    const int row = r0 + w * 16 + g;
#pragma unroll
    for (int j = 0; j < NC / 8; j++) {
        uint32_t p01 = pack_h2(acc[j][0] * sc, acc[j][1] * sc);
        uint32_t p23 = pack_h2(acc[j][2] * sc, acc[j][3] * sc);
        int col = j * 8 + q4 * 2;
        __half* dst = o0;
        int cc = col;
        if (MODE == 1 && col >= 64) { dst = o1; cc = col - 64; }
        *(uint32_t*)(dst + (size_t)row * 64 + cc)       = p01;
        *(uint32_t*)(dst + (size_t)(row + 8) * 64 + cc) = p23;
    }
}

__global__ void __launch_bounds__(256, 2) proj_all(
    const float* __restrict__ x,    const float* __restrict__ Wq,
    const float* __restrict__ cond, const float* __restrict__ Wkv,
    __half* __restrict__ q, __half* __restrict__ k, __half* __restrict__ v)
{
    extern __shared__ char sm[];
    if (blockIdx.x < 128) proj_body<64, 0>(sm, x, Wq, q, nullptr, blockIdx.x);
    else                  proj_body<128, 1>(sm, cond, Wkv, k, v, blockIdx.x - 128);
}

// ---------------------------------------------------------------------------
// Attention (fp16): 1 CTA = 64 q-rows, 4 warps 2x2 (mw x kw), 2 CTAs/SM.
// Software-pipelined mainloop: PV lags S/exp by one 16-key group, so
//   - kb LDSM latency hides behind PV MMAs of previous group
//   - exp chain hides behind next group's LDSM + S MMAs
// Q pre-scaled by 0.125*log2e -> s is already in exp2 domain (no FMUL).
// ---------------------------------------------------------------------------
__device__ __forceinline__ void issue_tile(
    uint32_t sb, uint32_t buf, int nt, int t,
    const uint4* k4, const uint4* v4)
{
    const uint4* k = k4 + nt * 1024;
    const uint4* v = v4 + nt * 1024;
#pragma unroll
    for (int i = t; i < 1024; i += 128) {
        int row = i >> 3, c = i & 7;
        uint32_t off = buf + (uint32_t)(row * 128)
                     + (uint32_t)((c * 16) ^ ((row & 7) << 4));
        CP_ASYNC16(sb + off,         k + i);
        CP_ASYNC16(sb + off + 16384, v + i);
    }
}

__global__ void __launch_bounds__(128, 2) attn_kernel(
    const __half* __restrict__ Q, const __half* __restrict__ K,
    const __half* __restrict__ V, float* __restrict__ O)
{
    extern __shared__ char smem[];
    const uint32_t sb = smem_u32(smem);

    const int t    = threadIdx.x;
    const int w    = t >> 5, lane = t & 31;
    const int mw   = w >> 1, kw = w & 1;
    const int g    = lane >> 2, q4 = lane & 3;
    const int mat  = lane >> 3, r = lane & 7;
    const int bb   = blockIdx.y;
    const int m0   = blockIdx.x * 64;

    // ---- stage Q into stage0, load A-frags ----
    {
        const uint4* q4p = (const uint4*)(Q + ((size_t)(bb * MDIM + m0)) * 64);
#pragma unroll
        for (int i = t; i < 512; i += 128) {
            int row = i >> 3, c = i & 7;
            uint32_t off = (uint32_t)(row * 128) + (uint32_t)((c * 16) ^ ((row & 7) << 4));
            *(uint4*)(smem + off) = q4p[i];
        }
    }
    __syncthreads();

    uint32_t qh[2][4][4];
#pragma unroll
    for (int mt = 0; mt < 2; mt++)
#pragma unroll
        for (int kf = 0; kf < 4; kf++) {
            uint32_t off = (uint32_t)((mw * 32 + mt * 16 + (mat & 1) * 8 + r) * 128)
                         + (uint32_t)((kf * 32 + (mat >> 1) * 16) ^ (r << 4));
            LDSM_X4(qh[mt][kf][0], qh[mt][kf][1], qh[mt][kf][2], qh[mt][kf][3],
                    sb + off);
        }
    __syncthreads();

    float oacc[2][8][4];
#pragma unroll
    for (int mt = 0; mt < 2; mt++)
#pragma unroll
        for (int n = 0; n < 8; n++)
#pragma unroll
            for (int j = 0; j < 4; j++) oacc[mt][n][j] = 0.f;
    float ll[2][2] = {{0.f, 0.f}, {0.f, 0.f}};

    const uint4* k4 = (const uint4*)(K + (size_t)(bb * NDIM) * 64);
    const uint4* v4 = (const uint4*)(V + (size_t)(bb * NDIM) * 64);

    issue_tile(sb, 0,     0, t, k4, v4); CP_COMMIT();
    issue_tile(sb, 32768, 1, t, k4, v4); CP_COMMIT();
    issue_tile(sb, 65536, 2, t, k4, v4); CP_COMMIT();

    for (int nt = 0; nt < NDIM / 128; ++nt) {
        CP_WAIT2();
        __syncthreads();
        const uint32_t buf = (uint32_t)(nt % 3) * 32768u;

        uint32_t pa[2][4];    // P frags of previous key group
        uint32_t vb[4][4];    // V frags of previous key group

        // 5 pipeline steps: step tp does S/exp for group tp (tp<4)
        // and PV for group tp-1 (tp>0).
#pragma unroll
        for (int tp = 0; tp < 5; tp++) {
            // ---- load V frags for PREVIOUS group ----
            if (tp > 0) {
                const int kgp = kw * 4 + tp - 1;
                const uint32_t rowa = (uint32_t)((kgp * 16 + (mat & 1) * 8 + r) * 128);
#pragma unroll
                for (int hp = 0; hp < 4; hp++) {
                    uint32_t av = sb + buf + 16384 + rowa
                                + (uint32_t)((hp * 32 + (mat >> 1) * 16) ^ (r << 4));
                    LDSM_X4T(vb[hp][0], vb[hp][1], vb[hp][2], vb[hp][3], av);
                }
            }

            // ---- load K frags for CURRENT group ----
            uint32_t kb[4][4];
            if (tp < 4) {
                const int kg = kw * 4 + tp;
                const uint32_t rowb = (uint32_t)((kg * 16 + (mat >> 1) * 8 + r) * 128);
#pragma unroll
                for (int kf = 0; kf < 4; kf++) {
                    uint32_t a = sb + buf + rowb
                               + (uint32_t)((kf * 32 + (mat & 1) * 16) ^ (r << 4));
                    LDSM_X4(kb[kf][0], kb[kf][1], kb[kf][2], kb[kf][3], a);
                }
            }

            // ---- PV for PREVIOUS group (covers kb LDSM latency) ----
            if (tp > 0) {
#pragma unroll
                for (int hp = 0; hp < 4; hp++)
#pragma unroll
                    for (int mt = 0; mt < 2; mt++) {
                        MMA_F16(oacc[mt][2 * hp],     pa[mt][0], pa[mt][1],
                                pa[mt][2], pa[mt][3], vb[hp][0], vb[hp][1]);
                        MMA_F16(oacc[mt][2 * hp + 1], pa[mt][0], pa[mt][1],
                                pa[mt][2], pa[mt][3], vb[hp][2], vb[hp][3]);
                    }
            }

            // ---- S + exp for CURRENT group ----
            if (tp < 4) {
                float s[2][2][4];
#pragma unroll
                for (int mt = 0; mt < 2; mt++) {
#pragma unroll
                    for (int nb = 0; nb < 2; nb++)
#pragma unroll
                        for (int j = 0; j < 4; j++) s[mt][nb][j] = 0.f;
#pragma unroll
                    for (int kf = 0; kf < 4; kf++) {
                        MMA_F16(s[mt][0], qh[mt][kf][0], qh[mt][kf][1],
                                qh[mt][kf][2], qh[mt][kf][3], kb[kf][0], kb[kf][1]);
                        MMA_F16(s[mt][1], qh[mt][kf][0], qh[mt][kf][1],
                                qh[mt][kf][2], qh[mt][kf][3], kb[kf][2], kb[kf][3]);
                    }
                }
#pragma unroll
                for (int mt = 0; mt < 2; mt++) {
                    float e00 = ex2f(s[mt][0][0]), e01 = ex2f(s[mt][0][1]);
                    float e02 = ex2f(s[mt][0][2]), e03 = ex2f(s[mt][0][3]);
                    float e10 = ex2f(s[mt][1][0]), e11 = ex2f(s[mt][1][1]);
                    float e12 = ex2f(s[mt][1][2]), e13 = ex2f(s[mt][1][3]);
                    ll[mt][0] += e00 + e01 + e10 + e11;
                    ll[mt][1] += e02 + e03 + e12 + e13;
                    pa[mt][0] = pack_h2(e00, e01); pa[mt][1] = pack_h2(e02, e03);
                    pa[mt][2] = pack_h2(e10, e11); pa[mt][3] = pack_h2(e12, e13);
                }
            }
        }

        __syncthreads();
        if (nt + 3 < NDIM / 128)
            issue_tile(sb, buf, nt + 3, t, k4, v4);
        CP_COMMIT();
    }

    // ---- epilogue: quad-reduce l, cross-kw smem reduction, store ----
#pragma unroll
    for (int mt = 0; mt < 2; mt++)
#pragma unroll
        for (int h = 0; h < 2; h++) {
            ll[mt][h] += __shfl_xor_sync(0xffffffffu, ll[mt][h], 1);
            ll[mt][h] += __shfl_xor_sync(0xffffffffu, ll[mt][h], 2);
        }

    __syncthreads();
    float* Osm = (float*)smem;             // [64 rows][64 cols]
    float* lsm = (float*)(smem + 16384);   // [64 rows]

    if (kw == 1) {
#pragma unroll
        for (int mt = 0; mt < 2; mt++) {
            int rr = mw * 32 + mt * 16 + g;
            float* d0 = Osm + rr * 64;
            float* d1 = d0 + 8 * 64;
#pragma unroll
            for (int n = 0; n < 8; n++) {
                int col = n * 8 + q4 * 2;
                *(float2*)(d0 + col) = make_float2(oacc[mt][n][0], oacc[mt][n][1]);
                *(float2*)(d1 + col) = make_float2(oacc[mt][n][2], oacc[mt][n][3]);
            }
            if (q4 == 0) {
                lsm[rr]     = ll[mt][0];
                lsm[rr + 8] = ll[mt][1];
            }
        }
    }
    __syncthreads();

    if (kw == 0) {
#pragma unroll
        for (int mt = 0; mt < 2; mt++) {
            int rr = mw * 32 + mt * 16 + g;
            const float* s0 = Osm + rr * 64;
            const float* s1 = s0 + 8 * 64;
            const float i0 = 1.f / (ll[mt][0] + lsm[rr]);
            const float i1 = 1.f / (ll[mt][1] + lsm[rr + 8]);
            float* Og0 = O + ((size_t)(bb * MDIM + m0 + rr)) * 64;
            float* Og1 = Og0 + 8 * 64;
#pragma unroll
            for (int n = 0; n < 8; n++) {
                int col = n * 8 + q4 * 2;
                float2 a0 = *(const float2*)(s0 + col);
                float2 a1 = *(const float2*)(s1 + col);
                *(float2*)(Og0 + col) = make_float2((oacc[mt][n][0] + a0.x) * i0,
                                                    (oacc[mt][n][1] + a0.y) * i0);
                *(float2*)(Og1 + col) = make_float2((oacc[mt][n][2] + a1.x) * i1,
                                                    (oacc[mt][n][3] + a1.y) * i1);
            }
        }
    }
}

// ---------------------------------------------------------------------------
// Launch
// ---------------------------------------------------------------------------
extern "C" void kernel_launch(void* const* d_in, const int* in_sizes, int n_in,
                              void* d_out, int out_size)
{
    const float* x    = (const float*)d_in[0];
    const float* cond = (const float*)d_in[1];
    const float* Wq   = (const float*)d_in[2];
    const float* Wkv  = (const float*)d_in[3];
    float* out = (float*)d_out;

    __half *q, *k, *v;
    cudaGetSymbolAddress((void**)&q, g_q);
    cudaGetSymbolAddress((void**)&k, g_k);
    cudaGetSymbolAddress((void**)&v, g_v);

    cudaFuncSetAttribute(proj_all,
                         cudaFuncAttributeMaxDynamicSharedMemorySize, 65536);
    cudaFuncSetAttribute(attn_kernel,
                         cudaFuncAttributeMaxDynamicSharedMemorySize, 98304);

    proj_all<<<256, 256, 65536>>>(x, Wq, cond, Wkv, q, k, v);

    dim3 grid(MDIM / 64, BATCH);
    attn_kernel<<<grid, 128, 98304>>>(q, k, v, out);
}